// round 2
// baseline (speedup 1.0000x reference)
#include <cuda_runtime.h>
#include <cuda_bf16.h>
#include <math_constants.h>

// Problem constants
#define BB 2
#define TT 2048
#define CC 2048
#define NQ 16
#define NKV 4
#define HD 128
#define ROWS (BB*TT)          // 4096
#define QW (NQ*HD)            // 2048
#define KW (NKV*HD)           // 512

// Scratch (allocation-free rule: __device__ globals)
__device__ float g_q[ROWS * QW];
__device__ float g_k[ROWS * KW];
__device__ float g_v[ROWS * KW];
__device__ float g_ctx[ROWS * QW];

// ---------------------------------------------------------------------------
// Classic fp32 SGEMM: C[M,N] = A[M,K] @ B[K,N]. 128x128 tile, BK=8, 8x8/thread.
// M % 128 == 0, N % 128 == 0, K % 8 == 0 (true for all our shapes).
// ---------------------------------------------------------------------------
__global__ __launch_bounds__(256, 2)
void sgemm_kernel(const float* __restrict__ A, const float* __restrict__ B,
                  float* __restrict__ C, int M, int N, int K) {
    __shared__ float As[8][128];
    __shared__ float Bs[8][128];

    const int tid = threadIdx.x;
    const int ty = tid >> 4;      // 0..15
    const int tx = tid & 15;      // 0..15
    const int rowBase = blockIdx.y * 128;
    const int colBase = blockIdx.x * 128;

    // A-load: 128 rows x 8 k, one float4 per thread (2 threads per row)
    const int a_row = tid >> 1;
    const int a_col = (tid & 1) << 2;
    // B-load: 8 rows x 128 cols, one float4 per thread
    const int b_row = tid >> 5;
    const int b_col = (tid & 31) << 2;

    float acc[8][8];
#pragma unroll
    for (int i = 0; i < 8; i++)
#pragma unroll
        for (int j = 0; j < 8; j++) acc[i][j] = 0.f;

    const float* Aptr = A + (size_t)(rowBase + a_row) * K + a_col;
    const float* Bptr = B + (size_t)b_row * N + colBase + b_col;

    for (int k0 = 0; k0 < K; k0 += 8) {
        float4 av = *reinterpret_cast<const float4*>(Aptr + k0);
        As[a_col + 0][a_row] = av.x;
        As[a_col + 1][a_row] = av.y;
        As[a_col + 2][a_row] = av.z;
        As[a_col + 3][a_row] = av.w;
        float4 bv = *reinterpret_cast<const float4*>(Bptr + (size_t)k0 * N);
        *reinterpret_cast<float4*>(&Bs[b_row][b_col]) = bv;
        __syncthreads();

#pragma unroll
        for (int kk = 0; kk < 8; kk++) {
            float a[8], b[8];
#pragma unroll
            for (int i = 0; i < 8; i++) a[i] = As[kk][ty * 8 + i];
#pragma unroll
            for (int j = 0; j < 8; j++) b[j] = Bs[kk][tx * 8 + j];
#pragma unroll
            for (int i = 0; i < 8; i++)
#pragma unroll
                for (int j = 0; j < 8; j++) acc[i][j] += a[i] * b[j];
        }
        __syncthreads();
    }

#pragma unroll
    for (int i = 0; i < 8; i++) {
        int r = rowBase + ty * 8 + i;
#pragma unroll
        for (int j = 0; j < 8; j += 4) {
            float4 o = make_float4(acc[i][j], acc[i][j+1], acc[i][j+2], acc[i][j+3]);
            *reinterpret_cast<float4*>(&C[(size_t)r * N + colBase + tx * 8 + j]) = o;
        }
    }
}

// ---------------------------------------------------------------------------
// Fused per-head RMSNorm + RoPE for q and k (in place). One warp per head-vec.
// ---------------------------------------------------------------------------
__global__ void rms_rope_kernel(const float* __restrict__ qw,
                                const float* __restrict__ kw,
                                const float* __restrict__ cosb,
                                const float* __restrict__ sinb) {
    const int warp = (blockIdx.x * blockDim.x + threadIdx.x) >> 5;
    const int lane = threadIdx.x & 31;
    const int NQVEC = ROWS * NQ;      // 65536
    const int NKVEC = ROWS * NKV;     // 16384
    if (warp >= NQVEC + NKVEC) return;

    float* base;
    const float* w;
    int t;
    if (warp < NQVEC) {
        int row = warp / NQ;
        t = row & (TT - 1);
        base = g_q + (size_t)row * QW + (warp % NQ) * HD;
        w = qw;
    } else {
        int v = warp - NQVEC;
        int row = v / NKV;
        t = row & (TT - 1);
        base = g_k + (size_t)row * KW + (v % NKV) * HD;
        w = kw;
    }

    float vals[4];
    float ss = 0.f;
#pragma unroll
    for (int j = 0; j < 4; j++) {
        vals[j] = base[lane + 32 * j];
        ss += vals[j] * vals[j];
    }
#pragma unroll
    for (int off = 16; off; off >>= 1) ss += __shfl_xor_sync(0xffffffffu, ss, off);
    float inv = rsqrtf(ss * (1.f / HD) + 1e-6f);

#pragma unroll
    for (int j = 0; j < 4; j++) vals[j] *= inv * w[lane + 32 * j];

    float c[4], s[4];
#pragma unroll
    for (int j = 0; j < 4; j++) {
        c[j] = cosb[t * HD + lane + 32 * j];
        s[j] = sinb[t * HD + lane + 32 * j];
    }
    float o0 = vals[0] * c[0] - vals[2] * s[0];
    float o1 = vals[1] * c[1] - vals[3] * s[1];
    float o2 = vals[2] * c[2] + vals[0] * s[2];
    float o3 = vals[3] * c[3] + vals[1] * s[3];
    base[lane +  0] = o0;
    base[lane + 32] = o1;
    base[lane + 64] = o2;
    base[lane + 96] = o3;
}

// ---------------------------------------------------------------------------
// fp32 flash attention, causal, GQA (4 q-heads per kv-head).
// Block: 256 threads handles one 64-row query tile of one (b, h).
// ---------------------------------------------------------------------------
#define FBM 64
#define FBN 64
#define QPITCH 132
#define SPITCH 65

__global__ __launch_bounds__(256, 2)
void flash_attn_kernel() {
    extern __shared__ float sm[];
    float* Qs  = sm;                         // 64 x 132
    float* KVs = Qs  + FBM * QPITCH;         // 64 x 132
    float* Ss  = KVs + FBN * QPITCH;         // 64 x 65
    float* m_s = Ss  + FBM * SPITCH;         // 64
    float* l_s = m_s + FBM;                  // 64
    float* a_s = l_s + FBM;                  // 64

    const int qt = blockIdx.x;
    const int h  = blockIdx.y;
    const int b  = blockIdx.z;
    const int hk = h >> 2;                   // NQ/NKV = 4
    const int tid = threadIdx.x;
    const int ty = tid >> 4;                 // 0..15 -> 4 rows each
    const int tx = tid & 15;                 // 0..15

    // Load Q tile (64 x 128)
    for (int i = tid; i < FBM * (HD / 4); i += 256) {
        int r = i >> 5, c4 = (i & 31) << 2;
        float4 qv = *reinterpret_cast<const float4*>(
            &g_q[((size_t)(b * TT) + qt * FBM + r) * QW + h * HD + c4]);
        *reinterpret_cast<float4*>(&Qs[r * QPITCH + c4]) = qv;
    }
    if (tid < FBM) { m_s[tid] = -CUDART_INF_F; l_s[tid] = 0.f; }

    float o[4][8];
#pragma unroll
    for (int i = 0; i < 4; i++)
#pragma unroll
        for (int j = 0; j < 8; j++) o[i][j] = 0.f;

    for (int kt = 0; kt <= qt; kt++) {
        __syncthreads();
        // Load K tile
        for (int i = tid; i < FBN * (HD / 4); i += 256) {
            int r = i >> 5, c4 = (i & 31) << 2;
            float4 kv = *reinterpret_cast<const float4*>(
                &g_k[((size_t)(b * TT) + kt * FBN + r) * KW + hk * HD + c4]);
            *reinterpret_cast<float4*>(&KVs[r * QPITCH + c4]) = kv;
        }
        __syncthreads();

        // S = Q K^T (each thread 4x4)
        float s[4][4];
#pragma unroll
        for (int i = 0; i < 4; i++)
#pragma unroll
            for (int j = 0; j < 4; j++) s[i][j] = 0.f;
        for (int d = 0; d < HD; d++) {
            float qr[4], kr[4];
#pragma unroll
            for (int i = 0; i < 4; i++) qr[i] = Qs[(4 * ty + i) * QPITCH + d];
#pragma unroll
            for (int j = 0; j < 4; j++) kr[j] = KVs[(4 * tx + j) * QPITCH + d];
#pragma unroll
            for (int i = 0; i < 4; i++)
#pragma unroll
                for (int j = 0; j < 4; j++) s[i][j] += qr[i] * kr[j];
        }
        const float sc = 0.08838834764831845f;   // 1/sqrt(128)
        const bool diag = (kt == qt);
#pragma unroll
        for (int i = 0; i < 4; i++) {
            int r = 4 * ty + i;
#pragma unroll
            for (int j = 0; j < 4; j++) {
                int cidx = 4 * tx + j;
                float val = s[i][j] * sc;
                if (diag && cidx > r) val = -1e9f;
                Ss[r * SPITCH + cidx] = val;
            }
        }
        __syncthreads();

        // Online softmax per row (thread-per-row)
        if (tid < FBM) {
            float mo = m_s[tid];
            float mn = mo;
            for (int j = 0; j < FBN; j++) mn = fmaxf(mn, Ss[tid * SPITCH + j]);
            float al = __expf(mo - mn);
            float lsum = 0.f;
            for (int j = 0; j < FBN; j++) {
                float e = __expf(Ss[tid * SPITCH + j] - mn);
                Ss[tid * SPITCH + j] = e;
                lsum += e;
            }
            m_s[tid] = mn;
            a_s[tid] = al;
            l_s[tid] = l_s[tid] * al + lsum;
        }
        __syncthreads();

        // Load V tile (overwrites K smem)
        for (int i = tid; i < FBN * (HD / 4); i += 256) {
            int r = i >> 5, c4 = (i & 31) << 2;
            float4 vv = *reinterpret_cast<const float4*>(
                &g_v[((size_t)(b * TT) + kt * FBN + r) * KW + hk * HD + c4]);
            *reinterpret_cast<float4*>(&KVs[r * QPITCH + c4]) = vv;
        }
        __syncthreads();

        // O = O*alpha + P @ V (each thread 4 rows x 8 cols)
        float alv[4];
#pragma unroll
        for (int i = 0; i < 4; i++) alv[i] = a_s[4 * ty + i];
#pragma unroll
        for (int i = 0; i < 4; i++)
#pragma unroll
            for (int j = 0; j < 8; j++) o[i][j] *= alv[i];
        for (int j = 0; j < FBN; j++) {
            float p[4];
#pragma unroll
            for (int i = 0; i < 4; i++) p[i] = Ss[(4 * ty + i) * SPITCH + j];
            float vv[8];
#pragma unroll
            for (int jj = 0; jj < 8; jj++) vv[jj] = KVs[j * QPITCH + 8 * tx + jj];
#pragma unroll
            for (int i = 0; i < 4; i++)
#pragma unroll
                for (int jj = 0; jj < 8; jj++) o[i][jj] += p[i] * vv[jj];
        }
    }

    // Epilogue: normalize and store to ctx [B,T,NQ*H]
#pragma unroll
    for (int i = 0; i < 4; i++) {
        int r = 4 * ty + i;
        float linv = 1.f / l_s[r];
        size_t rowoff = ((size_t)(b * TT) + qt * FBM + r) * QW + h * HD + 8 * tx;
#pragma unroll
        for (int jj = 0; jj < 8; jj += 4) {
            float4 ov = make_float4(o[i][jj] * linv, o[i][jj+1] * linv,
                                    o[i][jj+2] * linv, o[i][jj+3] * linv);
            *reinterpret_cast<float4*>(&g_ctx[rowoff + jj]) = ov;
        }
    }
}

// ---------------------------------------------------------------------------
// kernel_launch
// ---------------------------------------------------------------------------
extern "C" void kernel_launch(void* const* d_in, const int* in_sizes, int n_in,
                              void* d_out, int out_size) {
    const float* x    = (const float*)d_in[0];
    const float* Wq   = (const float*)d_in[1];
    const float* Wk   = (const float*)d_in[2];
    const float* Wv   = (const float*)d_in[3];
    const float* Wo   = (const float*)d_in[4];
    const float* qnw  = (const float*)d_in[5];
    const float* knw  = (const float*)d_in[6];
    const float* cosb = (const float*)d_in[7];
    const float* sinb = (const float*)d_in[8];
    float* out = (float*)d_out;

    float *qp, *kp, *vp, *ctxp;
    cudaGetSymbolAddress((void**)&qp,   g_q);
    cudaGetSymbolAddress((void**)&kp,   g_k);
    cudaGetSymbolAddress((void**)&vp,   g_v);
    cudaGetSymbolAddress((void**)&ctxp, g_ctx);

    // QKV projections
    sgemm_kernel<<<dim3(QW / 128, ROWS / 128), 256>>>(x, Wq, qp, ROWS, QW, CC);
    sgemm_kernel<<<dim3(KW / 128, ROWS / 128), 256>>>(x, Wk, kp, ROWS, KW, CC);
    sgemm_kernel<<<dim3(KW / 128, ROWS / 128), 256>>>(x, Wv, vp, ROWS, KW, CC);

    // RMSNorm + RoPE on q and k
    {
        int total_warps = ROWS * NQ + ROWS * NKV;   // 81920
        int blocks = (total_warps * 32 + 255) / 256;
        rms_rope_kernel<<<blocks, 256>>>(qnw, knw, cosb, sinb);
    }

    // Flash attention
    {
        int smem = (FBM * QPITCH + FBN * QPITCH + FBM * SPITCH + 3 * FBM) * sizeof(float);
        cudaFuncSetAttribute(flash_attn_kernel,
                             cudaFuncAttributeMaxDynamicSharedMemorySize, smem);
        flash_attn_kernel<<<dim3(TT / FBM, NQ, BB), 256, smem>>>();
    }

    // Output projection
    sgemm_kernel<<<dim3(CC / 128, ROWS / 128), 256>>>(ctxp, Wo, out, ROWS, CC, CC);
}